// round 16
// baseline (speedup 1.0000x reference)
#include <cuda_runtime.h>
#include <cuda_fp16.h>
#include <cstdint>
#include <math.h>

#define LEN 17821
#define DMODEL 384
#define HNUM 8
#define DH 48

// ---------------- scratch (device globals; no allocation) ----------------
__device__ __half g_srch[LEN * DMODEL];
__device__ __half g_qh[LEN * DMODEL];
__device__ __half g_valueh[LEN * DMODEL];
__device__ float g_off[LEN * 256];
__device__ float g_attn[LEN * 128];
__device__ __half g_msdah[LEN * DMODEL];
__device__ __half g_src2h[LEN * DMODEL];
__device__ __half g_xylnh[LEN * 256];
__device__ __half g_zdlnh[LEN * 128];
__device__ __half g_hxy[LEN * 256];
__device__ __half g_hzd[LEN * 128];
__device__ __half g_xy2h[LEN * 256];
__device__ __half g_zd2h[LEN * 128];
// converted weights, concatenated
#define WOFF_VAL   0
#define WOFF_OFF   (WOFF_VAL + 384 * 384)
#define WOFF_ATTN  (WOFF_OFF + 256 * 384)
#define WOFF_OUT   (WOFF_ATTN + 128 * 384)
#define WOFF_FXY1  (WOFF_OUT + 384 * 384)
#define WOFF_FXY2  (WOFF_FXY1 + 256 * 256)
#define WOFF_FZD1  (WOFF_FXY2 + 256 * 256)
#define WOFF_FZD2  (WOFF_FZD1 + 128 * 128)
#define WTOTAL     (WOFF_FZD2 + 128 * 128)
__device__ __half g_Wh[WTOTAL];

// ---------------- fused init: weights fp32->fp16 (8 segments) + src/q prep ----------
struct WJobs { const float4* s[8]; int end4[8]; };

__global__ void init_kernel(WJobs J, __half2* wdst,
                            const float4* __restrict__ src, const float4* __restrict__ pos,
                            __half2* __restrict__ srch, __half2* __restrict__ qh,
                            int n4, int wtotal4) {
    int i = blockIdx.x * blockDim.x + threadIdx.x;
    if (i < wtotal4) {
        int j = 0;
#pragma unroll
        for (int k = 0; k < 7; k++) j += (i >= J.end4[k]);
        int base = j ? J.end4[j - 1] : 0;
        float4 v = J.s[j][i - base];
        wdst[(size_t)i * 2]     = __floats2half2_rn(v.x, v.y);
        wdst[(size_t)i * 2 + 1] = __floats2half2_rn(v.z, v.w);
        return;
    }
    int p = i - wtotal4;
    if (p >= n4) return;
    float4 s = src[p], q = pos[p];
    srch[2 * p]     = __floats2half2_rn(s.x, s.y);
    srch[2 * p + 1] = __floats2half2_rn(s.z, s.w);
    qh[2 * p]       = __floats2half2_rn(s.x + q.x, s.y + q.y);
    qh[2 * p + 1]   = __floats2half2_rn(s.z + q.z, s.w + q.w);
}

// ================= batched FP16 tensor-core GEMM (BK=32, 3-stage — R13 config) ========
#define BM 64
#define BN 64
#define BKH 32
#define STAGES 3
#define HST 40

struct GemmJob {
    const __half* X;
    const __half* W;
    const float* bias;
    void* Y;
    int N, K;
    int relu, outhalf;
    int tiles_n;
    int tile_start;
};
struct Jobs3 { GemmJob j[3]; };

__device__ __forceinline__ void cp_async16(void* smem_dst, const void* gmem_src, bool pred) {
    uint32_t dst = (uint32_t)__cvta_generic_to_shared(smem_dst);
    int sz = pred ? 16 : 0;
    asm volatile("cp.async.cg.shared.global [%0], [%1], 16, %2;\n"
                 :: "r"(dst), "l"(gmem_src), "r"(sz));
}

#define LDSM_X4(r, addr)                                                         \
    asm volatile("ldmatrix.sync.aligned.m8n8.x4.shared.b16 {%0,%1,%2,%3}, [%4];" \
                 : "=r"((r)[0]), "=r"((r)[1]), "=r"((r)[2]), "=r"((r)[3])        \
                 : "r"(addr))

__global__ __launch_bounds__(128)
void h16_gemm_multi(Jobs3 jobs, int njobs, int M)
{
    __shared__ __align__(16) __half As[STAGES][BM * HST];
    __shared__ __align__(16) __half Bs[STAGES][BN * HST];

    GemmJob jb = jobs.j[0];
    int bid = blockIdx.x;
    if (njobs > 1 && bid >= jobs.j[1].tile_start) jb = jobs.j[1];
    if (njobs > 2 && bid >= jobs.j[2].tile_start) jb = jobs.j[2];
    const int tl = bid - jb.tile_start;
    const int nt = tl % jb.tiles_n;
    const int mtile = tl / jb.tiles_n;
    const int m0 = mtile * BM;
    const int n0 = nt * BN;
    const int N = jb.N, K = jb.K;
    const __half* __restrict__ X = jb.X;
    const __half* __restrict__ W = jb.W;

    const int tid = threadIdx.x;
    const int lane = tid & 31, w = tid >> 5;
    const int grp = lane >> 2, tig = lane & 3;
    const int wm0 = (w >> 1) * 32, wn0 = (w & 1) * 32;

    const int arow = tid >> 2;
    const int aq   = (tid & 3) * 8;
    const bool av0 = (m0 + arow) < M;
    const bool av1 = (m0 + arow + 32) < M;
    const int ar0 = av0 ? (m0 + arow) : (M - 1);
    const int ar1 = av1 ? (m0 + arow + 32) : (M - 1);
    const int br0 = n0 + arow;
    const int br1 = n0 + arow + 32;

    const int lrow = lane & 15;
    const int lcol = (lane >> 4) * 8;

    float acc[2][4][4];
#pragma unroll
    for (int mi = 0; mi < 2; mi++)
#pragma unroll
        for (int ni = 0; ni < 4; ni++)
#pragma unroll
            for (int i = 0; i < 4; i++) acc[mi][ni][i] = 0.f;

    const int KT = K / BKH;

#define LOAD_STAGE(kt_)                                                               \
    {                                                                                 \
        int buf_ = (kt_) % STAGES;                                                    \
        int k0_  = (kt_) * BKH;                                                       \
        cp_async16(&As[buf_][arow * HST + aq],        X + (size_t)ar0 * K + k0_ + aq, av0); \
        cp_async16(&As[buf_][(arow + 32) * HST + aq], X + (size_t)ar1 * K + k0_ + aq, av1); \
        cp_async16(&Bs[buf_][arow * HST + aq],        W + (size_t)br0 * K + k0_ + aq, true); \
        cp_async16(&Bs[buf_][(arow + 32) * HST + aq], W + (size_t)br1 * K + k0_ + aq, true); \
        asm volatile("cp.async.commit_group;\n");                                     \
    }

#pragma unroll
    for (int s = 0; s < STAGES - 1; s++) LOAD_STAGE(s);

    for (int kt = 0; kt < KT; kt++) {
        asm volatile("cp.async.wait_group %0;\n" :: "n"(STAGES - 2));
        __syncthreads();

        if (kt + STAGES - 1 < KT) {
            LOAD_STAGE(kt + STAGES - 1);
        } else {
            asm volatile("cp.async.commit_group;\n");
        }

        const __half* Ab = As[kt % STAGES];
        const __half* Bb = Bs[kt % STAGES];
#pragma unroll
        for (int ks = 0; ks < 2; ks++) {
            const int kk = ks * 16;
            uint32_t a[2][4], bfr[2][4];
#pragma unroll
            for (int mi = 0; mi < 2; mi++) {
                uint32_t ad = (uint32_t)__cvta_generic_to_shared(
                    &Ab[(wm0 + mi * 16 + lrow) * HST + kk + lcol]);
                LDSM_X4(a[mi], ad);
            }
#pragma unroll
            for (int np = 0; np < 2; np++) {
                uint32_t ad = (uint32_t)__cvta_generic_to_shared(
                    &Bb[(wn0 + np * 16 + lrow) * HST + kk + lcol]);
                LDSM_X4(bfr[np], ad);
            }
#pragma unroll
            for (int mi = 0; mi < 2; mi++)
#pragma unroll
                for (int ni = 0; ni < 4; ni++) {
                    uint32_t b0 = bfr[ni >> 1][(ni & 1)];
                    uint32_t b1 = bfr[ni >> 1][(ni & 1) + 2];
                    asm volatile(
                        "mma.sync.aligned.m16n8k16.row.col.f32.f16.f16.f32 "
                        "{%0,%1,%2,%3}, {%4,%5,%6,%7}, {%8,%9}, {%0,%1,%2,%3};\n"
                        : "+f"(acc[mi][ni][0]), "+f"(acc[mi][ni][1]),
                          "+f"(acc[mi][ni][2]), "+f"(acc[mi][ni][3])
                        : "r"(a[mi][0]), "r"(a[mi][1]), "r"(a[mi][2]), "r"(a[mi][3]),
                          "r"(b0), "r"(b1));
                }
        }
    }

    const int relu = jb.relu, outhalf = jb.outhalf;
#pragma unroll
    for (int mi = 0; mi < 2; mi++) {
#pragma unroll
        for (int i = 0; i < 2; i++) {
            int m = m0 + wm0 + mi * 16 + grp + i * 8;
            if (m >= M) continue;
#pragma unroll
            for (int ni = 0; ni < 4; ni++) {
                int n = n0 + wn0 + ni * 8 + tig * 2;
                float v0 = acc[mi][ni][i * 2 + 0] + jb.bias[n];
                float v1 = acc[mi][ni][i * 2 + 1] + jb.bias[n + 1];
                if (relu) { v0 = fmaxf(v0, 0.f); v1 = fmaxf(v1, 0.f); }
                if (outhalf) {
                    *reinterpret_cast<__half2*>((__half*)jb.Y + (size_t)m * N + n) =
                        __floats2half2_rn(v0, v1);
                } else {
                    *reinterpret_cast<float2*>((float*)jb.Y + (size_t)m * N + n) =
                        make_float2(v0, v1);
                }
            }
        }
    }
#undef LOAD_STAGE
}

// ---------------- msda: 8 queries/block (384 thr), ushort4 pixel offsets ----------
__global__ __launch_bounds__(384, 4)
void msda_kernel(const __half* __restrict__ value, const float* __restrict__ off,
                 const float* __restrict__ logits, const float* __restrict__ ref,
                 __half* __restrict__ out)
{
    const int HlA[4] = {100, 50, 25, 13};
    const int WlA[4] = {134, 67, 34, 17};
    const int stA[4] = {0, 13400, 16750, 17600};
    const float invW[4] = {1.f / 134.f, 1.f / 67.f, 1.f / 34.f, 1.f / 17.f};
    const float invH[4] = {1.f / 100.f, 1.f / 50.f, 1.f / 25.f, 1.f / 13.f};

    int tid = threadIdx.x;
    int sub = tid / 48;              // 0..7
    int t = tid % 48;
    int q = blockIdx.x * 8 + sub;
    int head = t / 6;
    int lane = t % 6;
    int c0 = lane * 8;

    __shared__ float  s_attn[8][128];
    __shared__ float  s_ref[8][8];
    __shared__ ushort4 s_pix[8][8][16];
    __shared__ uint2  s_w[8][8][16];

    int qb = blockIdx.x * 8;
    for (int i = tid; i < 1024; i += 384) {
        int s = i >> 7, j = i & 127;
        int qq = min(qb + s, LEN - 1);
        s_attn[s][j] = logits[(size_t)qq * 128 + j];
    }
    if (tid < 64) {
        int s = tid >> 3, j = tid & 7;
        int qq = min(qb + s, LEN - 1);
        s_ref[s][j] = ref[(size_t)qq * 8 + j];
    }
    __syncthreads();

    if (tid < 64) {
        int s = tid >> 3, h = tid & 7;
        float* p = &s_attn[s][h * 16];
        float mx = -1e30f;
#pragma unroll
        for (int i = 0; i < 16; i++) mx = fmaxf(mx, p[i]);
        float sum = 0.f;
        float v[16];
#pragma unroll
        for (int i = 0; i < 16; i++) { v[i] = __expf(p[i] - mx); sum += v[i]; }
        float inv = 1.f / sum;
#pragma unroll
        for (int i = 0; i < 16; i++) p[i] = v[i] * inv;
    }

    for (int i = tid; i < 1024; i += 384) {
        int s = i >> 7;
        int rem = i & 127;
        int hd = rem >> 4;
        int pt = rem & 15;
        int l = pt >> 2;
        int qq = min(qb + s, LEN - 1);
        float2 o2 = *reinterpret_cast<const float2*>(&off[(size_t)qq * 256 + rem * 2]);
        float fw = (float)WlA[l], fh = (float)HlA[l];
        float x = (s_ref[s][l * 2 + 0] + o2.x * invW[l]) * fw - 0.5f;
        float y = (s_ref[s][l * 2 + 1] + o2.y * invH[l]) * fh - 0.5f;
        float x0f = floorf(x), y0f = floorf(y);
        float dx = x - x0f, dy = y - y0f;
        int x0 = (int)x0f, y0 = (int)y0f;
        float wb0 = (1.f - dx) * (1.f - dy);
        float wb1 = dx * (1.f - dy);
        float wb2 = (1.f - dx) * dy;
        float wb3 = dx * dy;
        int Wli = WlA[l], Hli = HlA[l], st = stA[l];
        ushort4 pix;
        uint2 wpk;
        {
            bool vx0 = (x0 >= 0) & (x0 < Wli), vx1 = (x0 + 1 >= 0) & (x0 + 1 < Wli);
            bool vy0 = (y0 >= 0) & (y0 < Hli), vy1 = (y0 + 1 >= 0) & (y0 + 1 < Hli);
            bool v00 = vx0 & vy0, v10 = vx1 & vy0, v01 = vx0 & vy1, v11 = vx1 & vy1;
            int r0 = st + y0 * Wli, r1 = r0 + Wli;
            pix.x = (unsigned short)(v00 ? (r0 + x0) : 0);
            pix.y = (unsigned short)(v10 ? (r0 + x0 + 1) : 0);
            pix.z = (unsigned short)(v01 ? (r1 + x0) : 0);
            pix.w = (unsigned short)(v11 ? (r1 + x0 + 1) : 0);
            __half2 h01 = __halves2half2(__float2half_rn(v00 ? wb0 : 0.f),
                                         __float2half_rn(v10 ? wb1 : 0.f));
            __half2 h23 = __halves2half2(__float2half_rn(v01 ? wb2 : 0.f),
                                         __float2half_rn(v11 ? wb3 : 0.f));
            wpk.x = *reinterpret_cast<uint32_t*>(&h01);
            wpk.y = *reinterpret_cast<uint32_t*>(&h23);
        }
        s_pix[s][hd][pt] = pix;
        s_w[s][hd][pt] = wpk;
    }
    __syncthreads();

    if (q >= LEN) return;

    const __half* vb = value + head * DH + c0;

    float acc[8];
#pragma unroll
    for (int i = 0; i < 8; i++) acc[i] = 0.f;

#pragma unroll 4
    for (int pt = 0; pt < 16; pt++) {
        ushort4 pix = s_pix[sub][head][pt];
        uint2 wpk = s_w[sub][head][pt];
        float a = s_attn[sub][head * 16 + pt];

        __half2 w01 = *reinterpret_cast<__half2*>(&wpk.x);
        __half2 w23 = *reinterpret_cast<__half2*>(&wpk.y);
        __half2 wc[4];
        wc[0] = __half2half2(__low2half(w01));
        wc[1] = __half2half2(__high2half(w01));
        wc[2] = __half2half2(__low2half(w23));
        wc[3] = __half2half2(__high2half(w23));
        int oc[4];
        oc[0] = (int)pix.x * DMODEL;
        oc[1] = (int)pix.y * DMODEL;
        oc[2] = (int)pix.z * DMODEL;
        oc[3] = (int)pix.w * DMODEL;

        __half2 p0 = __float2half2_rn(0.f), p1 = p0, p2 = p0, p3 = p0;
#pragma unroll
        for (int c = 0; c < 4; c++) {
            uint4 gv = *reinterpret_cast<const uint4*>(vb + oc[c]);
            const __half2* h2 = reinterpret_cast<const __half2*>(&gv);
            p0 = __hfma2(h2[0], wc[c], p0);
            p1 = __hfma2(h2[1], wc[c], p1);
            p2 = __hfma2(h2[2], wc[c], p2);
            p3 = __hfma2(h2[3], wc[c], p3);
        }
        float2 f0 = __half22float2(p0), f1 = __half22float2(p1);
        float2 f2 = __half22float2(p2), f3 = __half22float2(p3);
        acc[0] = fmaf(f0.x, a, acc[0]); acc[1] = fmaf(f0.y, a, acc[1]);
        acc[2] = fmaf(f1.x, a, acc[2]); acc[3] = fmaf(f1.y, a, acc[3]);
        acc[4] = fmaf(f2.x, a, acc[4]); acc[5] = fmaf(f2.y, a, acc[5]);
        acc[6] = fmaf(f3.x, a, acc[6]); acc[7] = fmaf(f3.y, a, acc[7]);
    }

    uint4 pk;
    __half2* ph = reinterpret_cast<__half2*>(&pk);
#pragma unroll
    for (int j = 0; j < 4; j++) ph[j] = __floats2half2_rn(acc[2 * j], acc[2 * j + 1]);
    *reinterpret_cast<uint4*>(out + (size_t)q * DMODEL + head * DH + c0) = pk;
}

// ---------------- block reduction of 4 values (128 threads) ----------------
__device__ __forceinline__ void block_reduce4(float& a, float& b, float& c, float& d,
                                              float* sbuf) {
    unsigned mask = 0xffffffffu;
#pragma unroll
    for (int o = 16; o > 0; o >>= 1) {
        a += __shfl_down_sync(mask, a, o);
        b += __shfl_down_sync(mask, b, o);
        c += __shfl_down_sync(mask, c, o);
        d += __shfl_down_sync(mask, d, o);
    }
    int warp = threadIdx.x >> 5, lanei = threadIdx.x & 31;
    if (lanei == 0) {
        sbuf[warp * 4 + 0] = a; sbuf[warp * 4 + 1] = b;
        sbuf[warp * 4 + 2] = c; sbuf[warp * 4 + 3] = d;
    }
    __syncthreads();
    if (threadIdx.x == 0) {
        float ta = 0, tb = 0, tc = 0, td = 0;
        for (int w = 0; w < 4; w++) {
            ta += sbuf[w * 4 + 0]; tb += sbuf[w * 4 + 1];
            tc += sbuf[w * 4 + 2]; td += sbuf[w * 4 + 3];
        }
        sbuf[0] = ta; sbuf[1] = tb; sbuf[2] = tc; sbuf[3] = td;
    }
    __syncthreads();
    a = sbuf[0]; b = sbuf[1]; c = sbuf[2]; d = sbuf[3];
}

// ---------------- LN after attention: residual src(fp32) + src2(fp16), fp16 out ------
__global__ __launch_bounds__(128)
void ln1_kernel(const float* __restrict__ src, const __half* __restrict__ src2,
                const float* __restrict__ gxy, const float* __restrict__ bxy,
                const float* __restrict__ gzd, const float* __restrict__ bzd,
                __half* __restrict__ xyh, __half* __restrict__ zdh)
{
    __shared__ float sbuf[16];
    int q = blockIdx.x, t = threadIdx.x;
    size_t base = (size_t)q * DMODEL;
    float v0 = src[base + t]       + __half2float(src2[base + t]);
    float v1 = src[base + 128 + t] + __half2float(src2[base + 128 + t]);
    float v2 = src[base + 256 + t] + __half2float(src2[base + 256 + t]);
    float sxy = v0 + v1, sqxy = v0 * v0 + v1 * v1, szd = v2, sqzd = v2 * v2;
    block_reduce4(sxy, sqxy, szd, sqzd, sbuf);
    float mxy = sxy * (1.f / 256.f);
    float rxy = rsqrtf(sqxy * (1.f / 256.f) - mxy * mxy + 1e-5f);
    float mzd = szd * (1.f / 128.f);
    float rzd = rsqrtf(sqzd * (1.f / 128.f) - mzd * mzd + 1e-5f);
    float o0 = (v0 - mxy) * rxy * gxy[t]       + bxy[t];
    float o1 = (v1 - mxy) * rxy * gxy[128 + t] + bxy[128 + t];
    float o2 = (v2 - mzd) * rzd * gzd[t]       + bzd[t];
    xyh[(size_t)q * 256 + t]       = __float2half_rn(o0);
    xyh[(size_t)q * 256 + 128 + t] = __float2half_rn(o1);
    zdh[(size_t)q * 128 + t]       = __float2half_rn(o2);
}

// ---------------- final residual + LN (fp16 inputs), write fp32 output ----------------
__global__ __launch_bounds__(128)
void ln2_kernel(const __half* __restrict__ xyln, const __half* __restrict__ xy2,
                const __half* __restrict__ zdln, const __half* __restrict__ zd2,
                const float* __restrict__ gxy, const float* __restrict__ bxy,
                const float* __restrict__ gzd, const float* __restrict__ bzd,
                float* __restrict__ out)
{
    __shared__ float sbuf[16];
    int q = blockIdx.x, t = threadIdx.x;
    float v0 = __half2float(xyln[(size_t)q * 256 + t])       + __half2float(xy2[(size_t)q * 256 + t]);
    float v1 = __half2float(xyln[(size_t)q * 256 + 128 + t]) + __half2float(xy2[(size_t)q * 256 + 128 + t]);
    float v2 = __half2float(zdln[(size_t)q * 128 + t])       + __half2float(zd2[(size_t)q * 128 + t]);
    float sxy = v0 + v1, sqxy = v0 * v0 + v1 * v1, szd = v2, sqzd = v2 * v2;
    block_reduce4(sxy, sqxy, szd, sqzd, sbuf);
    float mxy = sxy * (1.f / 256.f);
    float rxy = rsqrtf(sqxy * (1.f / 256.f) - mxy * mxy + 1e-5f);
    float mzd = szd * (1.f / 128.f);
    float rzd = rsqrtf(sqzd * (1.f / 128.f) - mzd * mzd + 1e-5f);
    size_t ob = (size_t)q * DMODEL;
    out[ob + t]       = (v0 - mxy) * rxy * gxy[t]       + bxy[t];
    out[ob + 128 + t] = (v1 - mxy) * rxy * gxy[128 + t] + bxy[128 + t];
    out[ob + 256 + t] = (v2 - mzd) * rzd * gzd[t]       + bzd[t];
}

// ---------------- host launch ----------------
static inline GemmJob mkjob(const __half* X, const __half* W, const float* bias, void* Y,
                            int N, int K, int relu, int outhalf, int tile_start) {
    GemmJob j;
    j.X = X; j.W = W; j.bias = bias; j.Y = Y;
    j.N = N; j.K = K; j.relu = relu; j.outhalf = outhalf;
    j.tiles_n = N / BN; j.tile_start = tile_start;
    return j;
}

extern "C" void kernel_launch(void* const* d_in, const int* in_sizes, int n_in,
                              void* d_out, int out_size) {
    const float* src    = (const float*)d_in[0];
    const float* pos    = (const float*)d_in[3];
    const float* ref    = (const float*)d_in[4];
    const float* W_off  = (const float*)d_in[8];
    const float* b_off  = (const float*)d_in[9];
    const float* W_attn = (const float*)d_in[10];
    const float* b_attn = (const float*)d_in[11];
    const float* W_val  = (const float*)d_in[12];
    const float* b_val  = (const float*)d_in[13];
    const float* W_out  = (const float*)d_in[14];
    const float* b_out  = (const float*)d_in[15];
    const float* g1xy   = (const float*)d_in[16];
    const float* b1xy   = (const float*)d_in[17];
    const float* g1zd   = (const float*)d_in[18];
    const float* b1zd   = (const float*)d_in[19];
    const float* fxy_w1 = (const float*)d_in[20];
    const float* fxy_b1 = (const float*)d_in[21];
    const float* fxy_w2 = (const float*)d_in[22];
    const float* fxy_b2 = (const float*)d_in[23];
    const float* fxy_g  = (const float*)d_in[24];
    const float* fxy_b  = (const float*)d_in[25];
    const float* fzd_w1 = (const float*)d_in[26];
    const float* fzd_b1 = (const float*)d_in[27];
    const float* fzd_w2 = (const float*)d_in[28];
    const float* fzd_b2 = (const float*)d_in[29];
    const float* fzd_g  = (const float*)d_in[30];
    const float* fzd_b  = (const float*)d_in[31];
    float* out = (float*)d_out;

    __half *srch, *qh, *valueh, *msdah, *src2h, *xylnh, *zdlnh, *hxy, *hzd, *xy2h, *zd2h, *Wh;
    float *off, *attn;
    cudaGetSymbolAddress((void**)&srch, g_srch);
    cudaGetSymbolAddress((void**)&qh, g_qh);
    cudaGetSymbolAddress((void**)&valueh, g_valueh);
    cudaGetSymbolAddress((void**)&off, g_off);
    cudaGetSymbolAddress((void**)&attn, g_attn);
    cudaGetSymbolAddress((void**)&msdah, g_msdah);
    cudaGetSymbolAddress((void**)&src2h, g_src2h);
    cudaGetSymbolAddress((void**)&xylnh, g_xylnh);
    cudaGetSymbolAddress((void**)&zdlnh, g_zdlnh);
    cudaGetSymbolAddress((void**)&hxy, g_hxy);
    cudaGetSymbolAddress((void**)&hzd, g_hzd);
    cudaGetSymbolAddress((void**)&xy2h, g_xy2h);
    cudaGetSymbolAddress((void**)&zd2h, g_zd2h);
    cudaGetSymbolAddress((void**)&Wh, g_Wh);

    // fused init: weight conversion + src/q prep (one launch)
    {
        WJobs J;
        const float* srcs[8] = {W_val, W_off, W_attn, W_out, fxy_w1, fxy_w2, fzd_w1, fzd_w2};
        const int sizes[8] = {384 * 384, 256 * 384, 128 * 384, 384 * 384,
                              256 * 256, 256 * 256, 128 * 128, 128 * 128};
        int acc4 = 0;
        for (int i = 0; i < 8; i++) {
            J.s[i] = (const float4*)srcs[i];
            acc4 += sizes[i] / 4;
            J.end4[i] = acc4;
        }
        int n4 = LEN * DMODEL / 4;
        int total = acc4 + n4;
        init_kernel<<<(total + 255) / 256, 256>>>(J, (__half2*)Wh,
                                                  (const float4*)src, (const float4*)pos,
                                                  (__half2*)srch, (__half2*)qh, n4, acc4);
    }

    const int mt = (LEN + BM - 1) / BM;   // 279

    // pass 1: value (half out), off, attn logits — one launch
    {
        Jobs3 J;
        int ts = 0;
        J.j[0] = mkjob(srch, Wh + WOFF_VAL, b_val, valueh, 384, 384, 0, 1, ts); ts += mt * (384 / BN);
        J.j[1] = mkjob(qh, Wh + WOFF_OFF, b_off, off, 256, 384, 0, 0, ts);      ts += mt * (256 / BN);
        J.j[2] = mkjob(qh, Wh + WOFF_ATTN, b_attn, attn, 128, 384, 0, 0, ts);   ts += mt * (128 / BN);
        h16_gemm_multi<<<ts, 128>>>(J, 3, LEN);
    }

    // msda with fused softmax + phase-A precompute (8 queries/block)
    msda_kernel<<<(LEN + 7) / 8, 384>>>(valueh, off, attn, ref, msdah);

    // pass 2: output projection (fp16 out)
    {
        Jobs3 J;
        J.j[0] = mkjob(msdah, Wh + WOFF_OUT, b_out, src2h, 384, 384, 0, 1, 0);
        J.j[1] = J.j[0]; J.j[2] = J.j[0];
        h16_gemm_multi<<<mt * (384 / BN), 128>>>(J, 1, LEN);
    }

    ln1_kernel<<<LEN, 128>>>(src, src2h, g1xy, b1xy, g1zd, b1zd, xylnh, zdlnh);

    // pass 3: FFN first linears (relu, half out)
    {
        Jobs3 J;
        int ts = 0;
        J.j[0] = mkjob(xylnh, Wh + WOFF_FXY1, fxy_b1, hxy, 256, 256, 1, 1, ts); ts += mt * (256 / BN);
        J.j[1] = mkjob(zdlnh, Wh + WOFF_FZD1, fzd_b1, hzd, 128, 128, 1, 1, ts); ts += mt * (128 / BN);
        J.j[2] = J.j[1];
        h16_gemm_multi<<<ts, 128>>>(J, 2, LEN);
    }

    // pass 4: FFN second linears (fp16 out)
    {
        Jobs3 J;
        int ts = 0;
        J.j[0] = mkjob(hxy, Wh + WOFF_FXY2, fxy_b2, xy2h, 256, 256, 0, 1, ts); ts += mt * (256 / BN);
        J.j[1] = mkjob(hzd, Wh + WOFF_FZD2, fzd_b2, zd2h, 128, 128, 0, 1, ts); ts += mt * (128 / BN);
        J.j[2] = J.j[1];
        h16_gemm_multi<<<ts, 128>>>(J, 2, LEN);
    }

    ln2_kernel<<<LEN, 128>>>(xylnh, xy2h, zdlnh, zd2h, fxy_g, fxy_b, fzd_g, fzd_b, out);
}

// round 17
// speedup vs baseline: 1.0683x; 1.0683x over previous
#include <cuda_runtime.h>
#include <cuda_fp16.h>
#include <cstdint>
#include <math.h>

#define LEN 17821
#define DMODEL 384
#define HNUM 8
#define DH 48

// ---------------- scratch (device globals; no allocation) ----------------
__device__ __half g_srch[LEN * DMODEL];
__device__ __half g_qh[LEN * DMODEL];
__device__ __half g_valueh[LEN * DMODEL];
__device__ float g_off[LEN * 256];
__device__ float g_attn[LEN * 128];
__device__ __half g_msdah[LEN * DMODEL];
__device__ __half g_src2h[LEN * DMODEL];
__device__ __half g_xylnh[LEN * 256];
__device__ __half g_zdlnh[LEN * 128];
__device__ __half g_hxy[LEN * 256];
__device__ __half g_hzd[LEN * 128];
__device__ __half g_xy2h[LEN * 256];
__device__ __half g_zd2h[LEN * 128];
// converted weights, concatenated
#define WOFF_VAL   0
#define WOFF_OFF   (WOFF_VAL + 384 * 384)
#define WOFF_ATTN  (WOFF_OFF + 256 * 384)
#define WOFF_OUT   (WOFF_ATTN + 128 * 384)
#define WOFF_FXY1  (WOFF_OUT + 384 * 384)
#define WOFF_FXY2  (WOFF_FXY1 + 256 * 256)
#define WOFF_FZD1  (WOFF_FXY2 + 256 * 256)
#define WOFF_FZD2  (WOFF_FZD1 + 128 * 128)
#define WTOTAL     (WOFF_FZD2 + 128 * 128)
__device__ __half g_Wh[WTOTAL];

// ---------------- weight fp32 -> fp16 conversion (one launch, 8 segments) ------------
struct WJobs { const float4* s[8]; int end4[8]; };

__global__ void wconv_kernel(WJobs J, __half2* dst) {
    int i = blockIdx.x * blockDim.x + threadIdx.x;
    if (i >= J.end4[7]) return;
    int j = 0;
#pragma unroll
    for (int k = 0; k < 7; k++) j += (i >= J.end4[k]);
    int base = j ? J.end4[j - 1] : 0;
    float4 v = J.s[j][i - base];
    dst[(size_t)i * 2]     = __floats2half2_rn(v.x, v.y);
    dst[(size_t)i * 2 + 1] = __floats2half2_rn(v.z, v.w);
}

// ---------------- prep: src -> half, q = src + pos -> half ----------------
__global__ void prep_kernel(const float4* __restrict__ src, const float4* __restrict__ pos,
                            __half2* __restrict__ srch, __half2* __restrict__ qh, int n4) {
    int i = blockIdx.x * blockDim.x + threadIdx.x;
    if (i >= n4) return;
    float4 s = src[i], p = pos[i];
    srch[2 * i]     = __floats2half2_rn(s.x, s.y);
    srch[2 * i + 1] = __floats2half2_rn(s.z, s.w);
    qh[2 * i]       = __floats2half2_rn(s.x + p.x, s.y + p.y);
    qh[2 * i + 1]   = __floats2half2_rn(s.z + p.z, s.w + p.w);
}

// ================= batched FP16 tensor-core GEMM =================
#define BM 64
#define BN 64
#define BKH 32
#define STAGES 3
#define HST 40

struct GemmJob {
    const __half* X;
    const __half* W;
    const float* bias;
    void* Y;
    int N, K;
    int relu, outhalf;
    int tiles_n;
    int tile_start;
};
struct Jobs3 { GemmJob j[3]; };

__device__ __forceinline__ void cp_async16(void* smem_dst, const void* gmem_src, bool pred) {
    uint32_t dst = (uint32_t)__cvta_generic_to_shared(smem_dst);
    int sz = pred ? 16 : 0;
    asm volatile("cp.async.cg.shared.global [%0], [%1], 16, %2;\n"
                 :: "r"(dst), "l"(gmem_src), "r"(sz));
}

#define LDSM_X4(r, addr)                                                         \
    asm volatile("ldmatrix.sync.aligned.m8n8.x4.shared.b16 {%0,%1,%2,%3}, [%4];" \
                 : "=r"((r)[0]), "=r"((r)[1]), "=r"((r)[2]), "=r"((r)[3])        \
                 : "r"(addr))

__global__ __launch_bounds__(128)
void h16_gemm_multi(Jobs3 jobs, int njobs, int M)
{
    __shared__ __align__(16) __half As[STAGES][BM * HST];
    __shared__ __align__(16) __half Bs[STAGES][BN * HST];

    GemmJob jb = jobs.j[0];
    int bid = blockIdx.x;
    if (njobs > 1 && bid >= jobs.j[1].tile_start) jb = jobs.j[1];
    if (njobs > 2 && bid >= jobs.j[2].tile_start) jb = jobs.j[2];
    const int tl = bid - jb.tile_start;
    const int nt = tl % jb.tiles_n;
    const int mtile = tl / jb.tiles_n;
    const int m0 = mtile * BM;
    const int n0 = nt * BN;
    const int N = jb.N, K = jb.K;
    const __half* __restrict__ X = jb.X;
    const __half* __restrict__ W = jb.W;

    const int tid = threadIdx.x;
    const int lane = tid & 31, w = tid >> 5;
    const int grp = lane >> 2, tig = lane & 3;
    const int wm0 = (w >> 1) * 32, wn0 = (w & 1) * 32;

    const int arow = tid >> 2;
    const int aq   = (tid & 3) * 8;
    const bool av0 = (m0 + arow) < M;
    const bool av1 = (m0 + arow + 32) < M;
    const int ar0 = av0 ? (m0 + arow) : (M - 1);
    const int ar1 = av1 ? (m0 + arow + 32) : (M - 1);
    const int br0 = n0 + arow;
    const int br1 = n0 + arow + 32;

    const int lrow = lane & 15;
    const int lcol = (lane >> 4) * 8;

    float acc[2][4][4];
#pragma unroll
    for (int mi = 0; mi < 2; mi++)
#pragma unroll
        for (int ni = 0; ni < 4; ni++)
#pragma unroll
            for (int i = 0; i < 4; i++) acc[mi][ni][i] = 0.f;

    const int KT = K / BKH;

#define LOAD_STAGE(kt_)                                                               \
    {                                                                                 \
        int buf_ = (kt_) % STAGES;                                                    \
        int k0_  = (kt_) * BKH;                                                       \
        cp_async16(&As[buf_][arow * HST + aq],        X + (size_t)ar0 * K + k0_ + aq, av0); \
        cp_async16(&As[buf_][(arow + 32) * HST + aq], X + (size_t)ar1 * K + k0_ + aq, av1); \
        cp_async16(&Bs[buf_][arow * HST + aq],        W + (size_t)br0 * K + k0_ + aq, true); \
        cp_async16(&Bs[buf_][(arow + 32) * HST + aq], W + (size_t)br1 * K + k0_ + aq, true); \
        asm volatile("cp.async.commit_group;\n");                                     \
    }

#pragma unroll
    for (int s = 0; s < STAGES - 1; s++) LOAD_STAGE(s);

    for (int kt = 0; kt < KT; kt++) {
        asm volatile("cp.async.wait_group %0;\n" :: "n"(STAGES - 2));
        __syncthreads();

        if (kt + STAGES - 1 < KT) {
            LOAD_STAGE(kt + STAGES - 1);
        } else {
            asm volatile("cp.async.commit_group;\n");
        }

        const __half* Ab = As[kt % STAGES];
        const __half* Bb = Bs[kt % STAGES];
#pragma unroll
        for (int ks = 0; ks < 2; ks++) {
            const int kk = ks * 16;
            uint32_t a[2][4], bfr[2][4];
#pragma unroll
            for (int mi = 0; mi < 2; mi++) {
                uint32_t ad = (uint32_t)__cvta_generic_to_shared(
                    &Ab[(wm0 + mi * 16 + lrow) * HST + kk + lcol]);
                LDSM_X4(a[mi], ad);
            }
#pragma unroll
            for (int np = 0; np < 2; np++) {
                uint32_t ad = (uint32_t)__cvta_generic_to_shared(
                    &Bb[(wn0 + np * 16 + lrow) * HST + kk + lcol]);
                LDSM_X4(bfr[np], ad);
            }
#pragma unroll
            for (int mi = 0; mi < 2; mi++)
#pragma unroll
                for (int ni = 0; ni < 4; ni++) {
                    uint32_t b0 = bfr[ni >> 1][(ni & 1)];
                    uint32_t b1 = bfr[ni >> 1][(ni & 1) + 2];
                    asm volatile(
                        "mma.sync.aligned.m16n8k16.row.col.f32.f16.f16.f32 "
                        "{%0,%1,%2,%3}, {%4,%5,%6,%7}, {%8,%9}, {%0,%1,%2,%3};\n"
                        : "+f"(acc[mi][ni][0]), "+f"(acc[mi][ni][1]),
                          "+f"(acc[mi][ni][2]), "+f"(acc[mi][ni][3])
                        : "r"(a[mi][0]), "r"(a[mi][1]), "r"(a[mi][2]), "r"(a[mi][3]),
                          "r"(b0), "r"(b1));
                }
        }
    }

    const int relu = jb.relu, outhalf = jb.outhalf;
#pragma unroll
    for (int mi = 0; mi < 2; mi++) {
#pragma unroll
        for (int i = 0; i < 2; i++) {
            int m = m0 + wm0 + mi * 16 + grp + i * 8;
            if (m >= M) continue;
#pragma unroll
            for (int ni = 0; ni < 4; ni++) {
                int n = n0 + wn0 + ni * 8 + tig * 2;
                float v0 = acc[mi][ni][i * 2 + 0] + jb.bias[n];
                float v1 = acc[mi][ni][i * 2 + 1] + jb.bias[n + 1];
                if (relu) { v0 = fmaxf(v0, 0.f); v1 = fmaxf(v1, 0.f); }
                if (outhalf) {
                    *reinterpret_cast<__half2*>((__half*)jb.Y + (size_t)m * N + n) =
                        __floats2half2_rn(v0, v1);
                } else {
                    *reinterpret_cast<float2*>((float*)jb.Y + (size_t)m * N + n) =
                        make_float2(v0, v1);
                }
            }
        }
    }
#undef LOAD_STAGE
}

// ---------------- msda: 8 queries/block (384 thr), ushort4 pixel offsets ----------
__global__ __launch_bounds__(384, 4)
void msda_kernel(const __half* __restrict__ value, const float* __restrict__ off,
                 const float* __restrict__ logits, const float* __restrict__ ref,
                 __half* __restrict__ out)
{
    const int HlA[4] = {100, 50, 25, 13};
    const int WlA[4] = {134, 67, 34, 17};
    const int stA[4] = {0, 13400, 16750, 17600};
    const float invW[4] = {1.f / 134.f, 1.f / 67.f, 1.f / 34.f, 1.f / 17.f};
    const float invH[4] = {1.f / 100.f, 1.f / 50.f, 1.f / 25.f, 1.f / 13.f};

    int tid = threadIdx.x;
    int sub = tid / 48;              // 0..7
    int t = tid % 48;
    int q = blockIdx.x * 8 + sub;
    int head = t / 6;
    int lane = t % 6;
    int c0 = lane * 8;

    __shared__ float  s_attn[8][128];
    __shared__ float  s_ref[8][8];
    __shared__ ushort4 s_pix[8][8][16];
    __shared__ uint2  s_w[8][8][16];

    int qb = blockIdx.x * 8;
    for (int i = tid; i < 1024; i += 384) {
        int s = i >> 7, j = i & 127;
        int qq = min(qb + s, LEN - 1);
        s_attn[s][j] = logits[(size_t)qq * 128 + j];
    }
    if (tid < 64) {
        int s = tid >> 3, j = tid & 7;
        int qq = min(qb + s, LEN - 1);
        s_ref[s][j] = ref[(size_t)qq * 8 + j];
    }
    __syncthreads();

    if (tid < 64) {
        int s = tid >> 3, h = tid & 7;
        float* p = &s_attn[s][h * 16];
        float mx = -1e30f;
#pragma unroll
        for (int i = 0; i < 16; i++) mx = fmaxf(mx, p[i]);
        float sum = 0.f;
        float v[16];
#pragma unroll
        for (int i = 0; i < 16; i++) { v[i] = __expf(p[i] - mx); sum += v[i]; }
        float inv = 1.f / sum;
#pragma unroll
        for (int i = 0; i < 16; i++) p[i] = v[i] * inv;
    }

    for (int i = tid; i < 1024; i += 384) {
        int s = i >> 7;
        int rem = i & 127;
        int hd = rem >> 4;
        int pt = rem & 15;
        int l = pt >> 2;
        int qq = min(qb + s, LEN - 1);
        float2 o2 = *reinterpret_cast<const float2*>(&off[(size_t)qq * 256 + rem * 2]);
        float fw = (float)WlA[l], fh = (float)HlA[l];
        float x = (s_ref[s][l * 2 + 0] + o2.x * invW[l]) * fw - 0.5f;
        float y = (s_ref[s][l * 2 + 1] + o2.y * invH[l]) * fh - 0.5f;
        float x0f = floorf(x), y0f = floorf(y);
        float dx = x - x0f, dy = y - y0f;
        int x0 = (int)x0f, y0 = (int)y0f;
        float wb0 = (1.f - dx) * (1.f - dy);
        float wb1 = dx * (1.f - dy);
        float wb2 = (1.f - dx) * dy;
        float wb3 = dx * dy;
        int Wli = WlA[l], Hli = HlA[l], st = stA[l];
        ushort4 pix;
        uint2 wpk;
        {
            bool vx0 = (x0 >= 0) & (x0 < Wli), vx1 = (x0 + 1 >= 0) & (x0 + 1 < Wli);
            bool vy0 = (y0 >= 0) & (y0 < Hli), vy1 = (y0 + 1 >= 0) & (y0 + 1 < Hli);
            bool v00 = vx0 & vy0, v10 = vx1 & vy0, v01 = vx0 & vy1, v11 = vx1 & vy1;
            int r0 = st + y0 * Wli, r1 = r0 + Wli;
            pix.x = (unsigned short)(v00 ? (r0 + x0) : 0);
            pix.y = (unsigned short)(v10 ? (r0 + x0 + 1) : 0);
            pix.z = (unsigned short)(v01 ? (r1 + x0) : 0);
            pix.w = (unsigned short)(v11 ? (r1 + x0 + 1) : 0);
            __half2 h01 = __halves2half2(__float2half_rn(v00 ? wb0 : 0.f),
                                         __float2half_rn(v10 ? wb1 : 0.f));
            __half2 h23 = __halves2half2(__float2half_rn(v01 ? wb2 : 0.f),
                                         __float2half_rn(v11 ? wb3 : 0.f));
            wpk.x = *reinterpret_cast<uint32_t*>(&h01);
            wpk.y = *reinterpret_cast<uint32_t*>(&h23);
        }
        s_pix[s][hd][pt] = pix;
        s_w[s][hd][pt] = wpk;
    }
    __syncthreads();

    if (q >= LEN) return;

    const __half* vb = value + head * DH + c0;

    float acc[8];
#pragma unroll
    for (int i = 0; i < 8; i++) acc[i] = 0.f;

#pragma unroll 4
    for (int pt = 0; pt < 16; pt++) {
        ushort4 pix = s_pix[sub][head][pt];
        uint2 wpk = s_w[sub][head][pt];
        float a = s_attn[sub][head * 16 + pt];

        __half2 w01 = *reinterpret_cast<__half2*>(&wpk.x);
        __half2 w23 = *reinterpret_cast<__half2*>(&wpk.y);
        __half2 wc[4];
        wc[0] = __half2half2(__low2half(w01));
        wc[1] = __half2half2(__high2half(w01));
        wc[2] = __half2half2(__low2half(w23));
        wc[3] = __half2half2(__high2half(w23));
        int oc[4];
        oc[0] = (int)pix.x * DMODEL;
        oc[1] = (int)pix.y * DMODEL;
        oc[2] = (int)pix.z * DMODEL;
        oc[3] = (int)pix.w * DMODEL;

        __half2 p0 = __float2half2_rn(0.f), p1 = p0, p2 = p0, p3 = p0;
#pragma unroll
        for (int c = 0; c < 4; c++) {
            uint4 gv = *reinterpret_cast<const uint4*>(vb + oc[c]);
            const __half2* h2 = reinterpret_cast<const __half2*>(&gv);
            p0 = __hfma2(h2[0], wc[c], p0);
            p1 = __hfma2(h2[1], wc[c], p1);
            p2 = __hfma2(h2[2], wc[c], p2);
            p3 = __hfma2(h2[3], wc[c], p3);
        }
        float2 f0 = __half22float2(p0), f1 = __half22float2(p1);
        float2 f2 = __half22float2(p2), f3 = __half22float2(p3);
        acc[0] = fmaf(f0.x, a, acc[0]); acc[1] = fmaf(f0.y, a, acc[1]);
        acc[2] = fmaf(f1.x, a, acc[2]); acc[3] = fmaf(f1.y, a, acc[3]);
        acc[4] = fmaf(f2.x, a, acc[4]); acc[5] = fmaf(f2.y, a, acc[5]);
        acc[6] = fmaf(f3.x, a, acc[6]); acc[7] = fmaf(f3.y, a, acc[7]);
    }

    uint4 pk;
    __half2* ph = reinterpret_cast<__half2*>(&pk);
#pragma unroll
    for (int j = 0; j < 4; j++) ph[j] = __floats2half2_rn(acc[2 * j], acc[2 * j + 1]);
    *reinterpret_cast<uint4*>(out + (size_t)q * DMODEL + head * DH + c0) = pk;
}

// ---------------- block reduction of 4 values (128 threads) ----------------
__device__ __forceinline__ void block_reduce4(float& a, float& b, float& c, float& d,
                                              float* sbuf) {
    unsigned mask = 0xffffffffu;
#pragma unroll
    for (int o = 16; o > 0; o >>= 1) {
        a += __shfl_down_sync(mask, a, o);
        b += __shfl_down_sync(mask, b, o);
        c += __shfl_down_sync(mask, c, o);
        d += __shfl_down_sync(mask, d, o);
    }
    int warp = threadIdx.x >> 5, lanei = threadIdx.x & 31;
    if (lanei == 0) {
        sbuf[warp * 4 + 0] = a; sbuf[warp * 4 + 1] = b;
        sbuf[warp * 4 + 2] = c; sbuf[warp * 4 + 3] = d;
    }
    __syncthreads();
    if (threadIdx.x == 0) {
        float ta = 0, tb = 0, tc = 0, td = 0;
        for (int w = 0; w < 4; w++) {
            ta += sbuf[w * 4 + 0]; tb += sbuf[w * 4 + 1];
            tc += sbuf[w * 4 + 2]; td += sbuf[w * 4 + 3];
        }
        sbuf[0] = ta; sbuf[1] = tb; sbuf[2] = tc; sbuf[3] = td;
    }
    __syncthreads();
    a = sbuf[0]; b = sbuf[1]; c = sbuf[2]; d = sbuf[3];
}

// ---------------- LN after attention: residual src(fp32) + src2(fp16), fp16 out ------
__global__ __launch_bounds__(128)
void ln1_kernel(const float* __restrict__ src, const __half* __restrict__ src2,
                const float* __restrict__ gxy, const float* __restrict__ bxy,
                const float* __restrict__ gzd, const float* __restrict__ bzd,
                __half* __restrict__ xyh, __half* __restrict__ zdh)
{
    __shared__ float sbuf[16];
    int q = blockIdx.x, t = threadIdx.x;
    size_t base = (size_t)q * DMODEL;
    float v0 = src[base + t]       + __half2float(src2[base + t]);
    float v1 = src[base + 128 + t] + __half2float(src2[base + 128 + t]);
    float v2 = src[base + 256 + t] + __half2float(src2[base + 256 + t]);
    float sxy = v0 + v1, sqxy = v0 * v0 + v1 * v1, szd = v2, sqzd = v2 * v2;
    block_reduce4(sxy, sqxy, szd, sqzd, sbuf);
    float mxy = sxy * (1.f / 256.f);
    float rxy = rsqrtf(sqxy * (1.f / 256.f) - mxy * mxy + 1e-5f);
    float mzd = szd * (1.f / 128.f);
    float rzd = rsqrtf(sqzd * (1.f / 128.f) - mzd * mzd + 1e-5f);
    float o0 = (v0 - mxy) * rxy * gxy[t]       + bxy[t];
    float o1 = (v1 - mxy) * rxy * gxy[128 + t] + bxy[128 + t];
    float o2 = (v2 - mzd) * rzd * gzd[t]       + bzd[t];
    xyh[(size_t)q * 256 + t]       = __float2half_rn(o0);
    xyh[(size_t)q * 256 + 128 + t] = __float2half_rn(o1);
    zdh[(size_t)q * 128 + t]       = __float2half_rn(o2);
}

// ---------------- final residual + LN (fp16 inputs), write fp32 output ----------------
__global__ __launch_bounds__(128)
void ln2_kernel(const __half* __restrict__ xyln, const __half* __restrict__ xy2,
                const __half* __restrict__ zdln, const __half* __restrict__ zd2,
                const float* __restrict__ gxy, const float* __restrict__ bxy,
                const float* __restrict__ gzd, const float* __restrict__ bzd,
                float* __restrict__ out)
{
    __shared__ float sbuf[16];
    int q = blockIdx.x, t = threadIdx.x;
    float v0 = __half2float(xyln[(size_t)q * 256 + t])       + __half2float(xy2[(size_t)q * 256 + t]);
    float v1 = __half2float(xyln[(size_t)q * 256 + 128 + t]) + __half2float(xy2[(size_t)q * 256 + 128 + t]);
    float v2 = __half2float(zdln[(size_t)q * 128 + t])       + __half2float(zd2[(size_t)q * 128 + t]);
    float sxy = v0 + v1, sqxy = v0 * v0 + v1 * v1, szd = v2, sqzd = v2 * v2;
    block_reduce4(sxy, sqxy, szd, sqzd, sbuf);
    float mxy = sxy * (1.f / 256.f);
    float rxy = rsqrtf(sqxy * (1.f / 256.f) - mxy * mxy + 1e-5f);
    float mzd = szd * (1.f / 128.f);
    float rzd = rsqrtf(sqzd * (1.f / 128.f) - mzd * mzd + 1e-5f);
    size_t ob = (size_t)q * DMODEL;
    out[ob + t]       = (v0 - mxy) * rxy * gxy[t]       + bxy[t];
    out[ob + 128 + t] = (v1 - mxy) * rxy * gxy[128 + t] + bxy[128 + t];
    out[ob + 256 + t] = (v2 - mzd) * rzd * gzd[t]       + bzd[t];
}

// ---------------- host launch ----------------
static inline GemmJob mkjob(const __half* X, const __half* W, const float* bias, void* Y,
                            int N, int K, int relu, int outhalf, int tile_start) {
    GemmJob j;
    j.X = X; j.W = W; j.bias = bias; j.Y = Y;
    j.N = N; j.K = K; j.relu = relu; j.outhalf = outhalf;
    j.tiles_n = N / BN; j.tile_start = tile_start;
    return j;
}

extern "C" void kernel_launch(void* const* d_in, const int* in_sizes, int n_in,
                              void* d_out, int out_size) {
    const float* src    = (const float*)d_in[0];
    const float* pos    = (const float*)d_in[3];
    const float* ref    = (const float*)d_in[4];
    const float* W_off  = (const float*)d_in[8];
    const float* b_off  = (const float*)d_in[9];
    const float* W_attn = (const float*)d_in[10];
    const float* b_attn = (const float*)d_in[11];
    const float* W_val  = (const float*)d_in[12];
    const float* b_val  = (const float*)d_in[13];
    const float* W_out  = (const float*)d_in[14];
    const float* b_out  = (const float*)d_in[15];
    const float* g1xy   = (const float*)d_in[16];
    const float* b1xy   = (const float*)d_in[17];
    const float* g1zd   = (const float*)d_in[18];
    const float* b1zd   = (const float*)d_in[19];
    const float* fxy_w1 = (const float*)d_in[20];
    const float* fxy_b1 = (const float*)d_in[21];
    const float* fxy_w2 = (const float*)d_in[22];
    const float* fxy_b2 = (const float*)d_in[23];
    const float* fxy_g  = (const float*)d_in[24];
    const float* fxy_b  = (const float*)d_in[25];
    const float* fzd_w1 = (const float*)d_in[26];
    const float* fzd_b1 = (const float*)d_in[27];
    const float* fzd_w2 = (const float*)d_in[28];
    const float* fzd_b2 = (const float*)d_in[29];
    const float* fzd_g  = (const float*)d_in[30];
    const float* fzd_b  = (const float*)d_in[31];
    float* out = (float*)d_out;

    __half *srch, *qh, *valueh, *msdah, *src2h, *xylnh, *zdlnh, *hxy, *hzd, *xy2h, *zd2h, *Wh;
    float *off, *attn;
    cudaGetSymbolAddress((void**)&srch, g_srch);
    cudaGetSymbolAddress((void**)&qh, g_qh);
    cudaGetSymbolAddress((void**)&valueh, g_valueh);
    cudaGetSymbolAddress((void**)&off, g_off);
    cudaGetSymbolAddress((void**)&attn, g_attn);
    cudaGetSymbolAddress((void**)&msdah, g_msdah);
    cudaGetSymbolAddress((void**)&src2h, g_src2h);
    cudaGetSymbolAddress((void**)&xylnh, g_xylnh);
    cudaGetSymbolAddress((void**)&zdlnh, g_zdlnh);
    cudaGetSymbolAddress((void**)&hxy, g_hxy);
    cudaGetSymbolAddress((void**)&hzd, g_hzd);
    cudaGetSymbolAddress((void**)&xy2h, g_xy2h);
    cudaGetSymbolAddress((void**)&zd2h, g_zd2h);
    cudaGetSymbolAddress((void**)&Wh, g_Wh);

    // weight conversion (one launch)
    {
        WJobs J;
        const float* srcs[8] = {W_val, W_off, W_attn, W_out, fxy_w1, fxy_w2, fzd_w1, fzd_w2};
        const int sizes[8] = {384 * 384, 256 * 384, 128 * 384, 384 * 384,
                              256 * 256, 256 * 256, 128 * 128, 128 * 128};
        int acc4 = 0;
        for (int i = 0; i < 8; i++) {
            J.s[i] = (const float4*)srcs[i];
            acc4 += sizes[i] / 4;
            J.end4[i] = acc4;
        }
        wconv_kernel<<<(acc4 + 255) / 256, 256>>>(J, (__half2*)Wh);
    }

    int n4 = LEN * DMODEL / 4;
    prep_kernel<<<(n4 + 255) / 256, 256>>>((const float4*)src, (const float4*)pos,
                                           (__half2*)srch, (__half2*)qh, n4);

    const int mt = (LEN + BM - 1) / BM;   // 279

    // pass 1: value (half out), off, attn logits — one launch
    {
        Jobs3 J;
        int ts = 0;
        J.j[0] = mkjob(srch, Wh + WOFF_VAL, b_val, valueh, 384, 384, 0, 1, ts); ts += mt * (384 / BN);
        J.j[1] = mkjob(qh, Wh + WOFF_OFF, b_off, off, 256, 384, 0, 0, ts);      ts += mt * (256 / BN);
        J.j[2] = mkjob(qh, Wh + WOFF_ATTN, b_attn, attn, 128, 384, 0, 0, ts);   ts += mt * (128 / BN);
        h16_gemm_multi<<<ts, 128>>>(J, 3, LEN);
    }

    // msda with fused softmax + phase-A precompute (8 queries/block)
    msda_kernel<<<(LEN + 7) / 8, 384>>>(valueh, off, attn, ref, msdah);

    // pass 2: output projection (fp16 out)
    {
        Jobs3 J;
        J.j[0] = mkjob(msdah, Wh + WOFF_OUT, b_out, src2h, 384, 384, 0, 1, 0);
        J.j[1] = J.j[0]; J.j[2] = J.j[0];
        h16_gemm_multi<<<mt * (384 / BN), 128>>>(J, 1, LEN);
    }

    ln1_kernel<<<LEN, 128>>>(src, src2h, g1xy, b1xy, g1zd, b1zd, xylnh, zdlnh);

    // pass 3: FFN first linears (relu, half out)
    {
        Jobs3 J;
        int ts = 0;
        J.j[0] = mkjob(xylnh, Wh + WOFF_FXY1, fxy_b1, hxy, 256, 256, 1, 1, ts); ts += mt * (256 / BN);
        J.j[1] = mkjob(zdlnh, Wh + WOFF_FZD1, fzd_b1, hzd, 128, 128, 1, 1, ts); ts += mt * (128 / BN);
        J.j[2] = J.j[1];
        h16_gemm_multi<<<ts, 128>>>(J, 2, LEN);
    }

    // pass 4: FFN second linears (fp16 out)
    {
        Jobs3 J;
        int ts = 0;
        J.j[0] = mkjob(hxy, Wh + WOFF_FXY2, fxy_b2, xy2h, 256, 256, 0, 1, ts); ts += mt * (256 / BN);
        J.j[1] = mkjob(hzd, Wh + WOFF_FZD2, fzd_b2, zd2h, 128, 128, 0, 1, ts); ts += mt * (128 / BN);
        J.j[2] = J.j[1];
        h16_gemm_multi<<<ts, 128>>>(J, 2, LEN);
    }

    ln2_kernel<<<LEN, 128>>>(xylnh, xy2h, zdlnh, zd2h, fxy_g, fxy_b, fzd_g, fzd_b, out);
}